// round 1
// baseline (speedup 1.0000x reference)
#include <cuda_runtime.h>
#include <math.h>

// ---------------------------------------------------------------------------
// Problem constants
// ---------------------------------------------------------------------------
#define B_  2
#define T_  2048
#define D_  1024
#define NH_ 16
#define DH_ 64
#define FFN_ 2736
#define M_  (B_ * T_)          // 4096 rows
#define EPS_ 1e-6f

// ---------------------------------------------------------------------------
// Device scratch (no allocations allowed -> __device__ globals)
// ---------------------------------------------------------------------------
__device__ float s_glin[M_ * D_];
__device__ float s_xmix[M_ * D_];
__device__ float s_h   [M_ * D_];
__device__ float s_qkv [M_ * 3 * D_];
__device__ float s_dd  [M_ * NH_ * 16];
__device__ float s_qt  [B_ * NH_ * T_ * DH_];
__device__ float s_kt  [B_ * NH_ * T_ * DH_];
__device__ float s_vt  [B_ * NH_ * T_ * DH_];
__device__ float s_y   [M_ * D_];
__device__ float s_x2  [M_ * D_];
__device__ float s_gate[M_ * FFN_];
__device__ float s_up  [M_ * FFN_];

// ---------------------------------------------------------------------------
// GEMM: C[M,N] = A[M,K] @ W[N,K]^T (+bias) (+residual)
// 64x64 tile, BK=16, 256 threads, 4x4 microtile. M assumed %64==0.
// ---------------------------------------------------------------------------
__global__ __launch_bounds__(256) void gemm64(
    const float* __restrict__ A, const float* __restrict__ W,
    const float* __restrict__ bias, const float* __restrict__ res,
    float* __restrict__ C, int N, int K, int mode)
{
    __shared__ float As[16][64];
    __shared__ float Ws[16][64];
    const int tid = threadIdx.x;
    const int tx = tid & 15, ty = tid >> 4;
    const int lr = tid >> 2, lk = (tid & 3) << 2;
    const int m0 = blockIdx.y * 64, n0 = blockIdx.x * 64;

    const float* Ap = A + (size_t)(m0 + lr) * K + lk;
    const int wrow = n0 + lr;
    const float* Wp = W + (size_t)wrow * K + lk;
    const bool wv = (wrow < N);

    float acc[4][4] = {};
    for (int k0 = 0; k0 < K; k0 += 16) {
        float4 av = *(const float4*)(Ap + k0);
        float4 wvv = wv ? *(const float4*)(Wp + k0) : make_float4(0.f, 0.f, 0.f, 0.f);
        __syncthreads();
        As[lk + 0][lr] = av.x;  As[lk + 1][lr] = av.y;
        As[lk + 2][lr] = av.z;  As[lk + 3][lr] = av.w;
        Ws[lk + 0][lr] = wvv.x; Ws[lk + 1][lr] = wvv.y;
        Ws[lk + 2][lr] = wvv.z; Ws[lk + 3][lr] = wvv.w;
        __syncthreads();
        #pragma unroll
        for (int kk = 0; kk < 16; kk++) {
            float a[4], b[4];
            *(float4*)a = *(const float4*)&As[kk][ty * 4];
            *(float4*)b = *(const float4*)&Ws[kk][tx * 4];
            #pragma unroll
            for (int i = 0; i < 4; i++)
                #pragma unroll
                for (int j = 0; j < 4; j++)
                    acc[i][j] += a[i] * b[j];
        }
    }
    #pragma unroll
    for (int i = 0; i < 4; i++) {
        const int m = m0 + ty * 4 + i;
        #pragma unroll
        for (int j = 0; j < 4; j++) {
            const int n = n0 + tx * 4 + j;
            if (n < N) {
                float v = acc[i][j];
                if (mode & 1) v += bias[n];
                if (mode & 2) v += res[(size_t)m * N + n];
                C[(size_t)m * N + n] = v;
            }
        }
    }
}

// ---------------------------------------------------------------------------
// x_mix = (1-sigmoid(glin)) * x + sigmoid(glin) * x_prev   (x_prev = shift in T)
// ---------------------------------------------------------------------------
__global__ void mix_kernel(const float* __restrict__ x,
                           const float* __restrict__ glin,
                           float* __restrict__ out)
{
    const size_t i = (size_t)blockIdx.x * blockDim.x + threadIdx.x;  // float4 idx
    const int row = (int)(i >> 8);          // 256 float4 per row of 1024
    const int t = row & (T_ - 1);
    float4 xv = *(const float4*)(x + i * 4);
    float4 gv = *(const float4*)(glin + i * 4);
    float4 pv = make_float4(0.f, 0.f, 0.f, 0.f);
    if (t > 0) pv = *(const float4*)(x + (i - 256) * 4);
    float4 o;
    float g;
    g = 1.f / (1.f + __expf(-gv.x)); o.x = (1.f - g) * xv.x + g * pv.x;
    g = 1.f / (1.f + __expf(-gv.y)); o.y = (1.f - g) * xv.y + g * pv.y;
    g = 1.f / (1.f + __expf(-gv.z)); o.z = (1.f - g) * xv.z + g * pv.z;
    g = 1.f / (1.f + __expf(-gv.w)); o.w = (1.f - g) * xv.w + g * pv.w;
    *(float4*)(out + i * 4) = o;
}

// ---------------------------------------------------------------------------
// RMSNorm over D=1024, one block per row
// ---------------------------------------------------------------------------
__global__ __launch_bounds__(256) void rmsnorm_kernel(
    const float* __restrict__ x, const float* __restrict__ w,
    float* __restrict__ out)
{
    const int row = blockIdx.x;
    const int tid = threadIdx.x;
    const float* xr = x + (size_t)row * D_;
    float4 v = *(const float4*)(xr + tid * 4);
    float s = v.x * v.x + v.y * v.y + v.z * v.z + v.w * v.w;
    // warp reduce then block reduce
    #pragma unroll
    for (int m = 16; m > 0; m >>= 1) s += __shfl_xor_sync(0xffffffffu, s, m);
    __shared__ float red[8];
    if ((tid & 31) == 0) red[tid >> 5] = s;
    __syncthreads();
    if (tid < 32) {
        float t = (tid < 8) ? red[tid] : 0.f;
        #pragma unroll
        for (int m = 4; m > 0; m >>= 1) t += __shfl_xor_sync(0xffffffffu, t, m);
        if (tid == 0) red[0] = t;
    }
    __syncthreads();
    const float inv = rsqrtf(red[0] / (float)D_ + EPS_);
    float4 wv = *(const float4*)(w + tid * 4);
    float4 o;
    o.x = v.x * inv * wv.x; o.y = v.y * inv * wv.y;
    o.z = v.z * inv * wv.z; o.w = v.w * inv * wv.w;
    *(float4*)(out + (size_t)row * D_ + tid * 4) = o;
}

// ---------------------------------------------------------------------------
// In-place cumsum along T for dd angles: [B, T, 256] over T per channel
// ---------------------------------------------------------------------------
__global__ void cumsum_kernel(float* __restrict__ dd)
{
    const int c = threadIdx.x;          // 0..255
    const int b = blockIdx.x;
    float acc = 0.f;
    size_t base = (size_t)b * T_ * 256 + c;
    #pragma unroll 8
    for (int t = 0; t < T_; t++) {
        acc += dd[base];
        dd[base] = acc;
        base += 256;
    }
}

// ---------------------------------------------------------------------------
// Per (b,t,h): q/k head RMSNorm * post-bias, hybrid rope (fixed + dd cumsum),
// scatter q,k,v into head-major [B*NH, T, DH] layout. One warp per (b,t,h).
// ---------------------------------------------------------------------------
__global__ __launch_bounds__(256) void qkv_transform_kernel(
    const float* __restrict__ qkv, const float* __restrict__ ddcum,
    const float* __restrict__ rc, const float* __restrict__ rs,
    const float* __restrict__ qnw, const float* __restrict__ knw,
    const float* __restrict__ qpb, const float* __restrict__ kpb,
    float* __restrict__ qt, float* __restrict__ kt, float* __restrict__ vt)
{
    const int w = blockIdx.x * 8 + (threadIdx.x >> 5);
    const int lane = threadIdx.x & 31;
    const int b = w >> 15;                 // / (T*NH) = 32768
    const int rem = w & 32767;
    const int t = rem >> 4;
    const int h = rem & 15;

    const size_t base = ((size_t)(b * T_ + t) * 3) * D_ + h * DH_;
    float q0 = qkv[base + lane],          q1 = qkv[base + 32 + lane];
    float k0 = qkv[base + D_ + lane],     k1 = qkv[base + D_ + 32 + lane];
    float v0 = qkv[base + 2 * D_ + lane], v1 = qkv[base + 2 * D_ + 32 + lane];

    // head rms norms (over 64)
    float sq = q0 * q0 + q1 * q1;
    float sk = k0 * k0 + k1 * k1;
    #pragma unroll
    for (int m = 16; m > 0; m >>= 1) {
        sq += __shfl_xor_sync(0xffffffffu, sq, m);
        sk += __shfl_xor_sync(0xffffffffu, sk, m);
    }
    const float rq = rsqrtf(sq / 64.f + EPS_);
    const float rk = rsqrtf(sk / 64.f + EPS_);
    q0 *= rq * qnw[lane] * qpb[lane];
    q1 *= rq * qnw[lane + 32] * qpb[lane + 32];
    k0 *= rk * knw[lane] * kpb[lane];
    k1 *= rk * knw[lane + 32] * kpb[lane + 32];

    // hybrid rope
    const int j = lane & 15;
    const float c = rc[t * 32 + j], s = rs[t * 32 + j];
    const float ang = ddcum[((size_t)(b * T_ + t)) * 256 + h * 16 + j];
    float s2, c2;
    sincosf(ang, &s2, &c2);   // precise: angles can be O(100)

    const float qp0 = __shfl_xor_sync(0xffffffffu, q0, 16);
    const float qp1 = __shfl_xor_sync(0xffffffffu, q1, 16);
    const float kp0 = __shfl_xor_sync(0xffffffffu, k0, 16);
    const float kp1 = __shfl_xor_sync(0xffffffffu, k1, 16);
    float oq0, oq1, ok0, ok1;
    if (lane < 16) {
        oq0 = q0 * c - qp0 * s;  oq1 = q1 * c2 - qp1 * s2;
        ok0 = k0 * c - kp0 * s;  ok1 = k1 * c2 - kp1 * s2;
    } else {
        oq0 = q0 * c + qp0 * s;  oq1 = q1 * c2 + qp1 * s2;
        ok0 = k0 * c + kp0 * s;  ok1 = k1 * c2 + kp1 * s2;
    }

    const size_t ob = ((size_t)(b * NH_ + h) * T_ + t) * DH_;
    qt[ob + lane] = oq0;  qt[ob + 32 + lane] = oq1;
    kt[ob + lane] = ok0;  kt[ob + 32 + lane] = ok1;
    vt[ob + lane] = v0;   vt[ob + 32 + lane] = v1;
}

// ---------------------------------------------------------------------------
// Causal flash attention. One block per (q-tile of 64, b*h). DH=64.
// Dynamic smem: Qs[64][64] (transposed, pre-scaled), KPs[64][64] (K^T then P^T),
// Vs[64][64]. Online softmax, 4x4 microtiles, 256 threads.
// ---------------------------------------------------------------------------
__global__ __launch_bounds__(256) void flash_kernel(
    const float* __restrict__ qt, const float* __restrict__ kt,
    const float* __restrict__ vt, float* __restrict__ y)
{
    extern __shared__ float fsm[];
    float* Qs  = fsm;             // [d][m]
    float* KPs = fsm + 4096;      // [d][n]  then reused as P^T [n][m]
    float* Vs  = fsm + 8192;      // [n][d]

    const int tid = threadIdx.x;
    const int tx = tid & 15, ty = tid >> 4;
    const int bx = blockIdx.x;            // q tile index
    const int bh = blockIdx.y;            // b*NH + h
    const int b = bh >> 4, h = bh & 15;
    const int m0 = bx * 64;
    const int lr = tid >> 2, ld0 = (tid & 3) << 4;

    const float* Qb = qt + (size_t)bh * T_ * DH_;
    const float* Kb = kt + (size_t)bh * T_ * DH_;
    const float* Vb = vt + (size_t)bh * T_ * DH_;

    // load Q tile transposed + pre-scale by 1/sqrt(DH)
    {
        const float* src = Qb + (size_t)(m0 + lr) * DH_ + ld0;
        #pragma unroll
        for (int cch = 0; cch < 16; cch += 4) {
            float4 v = *(const float4*)(src + cch);
            Qs[(ld0 + cch + 0) * 64 + lr] = v.x * 0.125f;
            Qs[(ld0 + cch + 1) * 64 + lr] = v.y * 0.125f;
            Qs[(ld0 + cch + 2) * 64 + lr] = v.z * 0.125f;
            Qs[(ld0 + cch + 3) * 64 + lr] = v.w * 0.125f;
        }
    }

    float mi[4], li[4], O[4][4] = {};
    #pragma unroll
    for (int i = 0; i < 4; i++) { mi[i] = -1e30f; li[i] = 0.f; }

    for (int nt = 0; nt <= bx; nt++) {
        const int n0 = nt * 64;
        __syncthreads();   // protect KPs/Vs from previous iteration readers
        {
            const float* ks = Kb + (size_t)(n0 + lr) * DH_ + ld0;
            const float* vs = Vb + (size_t)(n0 + lr) * DH_ + ld0;
            #pragma unroll
            for (int cch = 0; cch < 16; cch += 4) {
                float4 kv = *(const float4*)(ks + cch);
                KPs[(ld0 + cch + 0) * 64 + lr] = kv.x;
                KPs[(ld0 + cch + 1) * 64 + lr] = kv.y;
                KPs[(ld0 + cch + 2) * 64 + lr] = kv.z;
                KPs[(ld0 + cch + 3) * 64 + lr] = kv.w;
                *(float4*)&Vs[lr * 64 + ld0 + cch] = *(const float4*)(vs + cch);
            }
        }
        __syncthreads();

        // S = Q K^T tile (pre-scaled)
        float S[4][4] = {};
        #pragma unroll 8
        for (int d = 0; d < 64; d++) {
            float a[4], bb[4];
            *(float4*)a  = *(const float4*)&Qs[d * 64 + ty * 4];
            *(float4*)bb = *(const float4*)&KPs[d * 64 + tx * 4];
            #pragma unroll
            for (int i = 0; i < 4; i++)
                #pragma unroll
                for (int jj = 0; jj < 4; jj++)
                    S[i][jj] += a[i] * bb[jj];
        }
        // causal mask on diagonal tile (m0 == n0 there)
        if (nt == bx) {
            #pragma unroll
            for (int i = 0; i < 4; i++)
                #pragma unroll
                for (int jj = 0; jj < 4; jj++)
                    if (tx * 4 + jj > ty * 4 + i) S[i][jj] = -1e30f;
        }
        // online softmax (rows are shared by 16 consecutive lanes)
        #pragma unroll
        for (int i = 0; i < 4; i++) {
            float mx = fmaxf(fmaxf(S[i][0], S[i][1]), fmaxf(S[i][2], S[i][3]));
            #pragma unroll
            for (int m = 1; m < 16; m <<= 1)
                mx = fmaxf(mx, __shfl_xor_sync(0xffffffffu, mx, m));
            const float mnew = fmaxf(mi[i], mx);
            const float corr = __expf(mi[i] - mnew);
            float rsum = 0.f;
            #pragma unroll
            for (int jj = 0; jj < 4; jj++) {
                S[i][jj] = __expf(S[i][jj] - mnew);
                rsum += S[i][jj];
            }
            #pragma unroll
            for (int m = 1; m < 16; m <<= 1)
                rsum += __shfl_xor_sync(0xffffffffu, rsum, m);
            li[i] = li[i] * corr + rsum;
            mi[i] = mnew;
            #pragma unroll
            for (int jj = 0; jj < 4; jj++) O[i][jj] *= corr;
        }
        __syncthreads();   // all done reading K from KPs
        // store P transposed: KPs[n][m]
        #pragma unroll
        for (int i = 0; i < 4; i++)
            #pragma unroll
            for (int jj = 0; jj < 4; jj++)
                KPs[(tx * 4 + jj) * 64 + ty * 4 + i] = S[i][jj];
        __syncthreads();
        // O += P V
        #pragma unroll 8
        for (int n = 0; n < 64; n++) {
            float p[4], v[4];
            *(float4*)p = *(const float4*)&KPs[n * 64 + ty * 4];
            *(float4*)v = *(const float4*)&Vs[n * 64 + tx * 4];
            #pragma unroll
            for (int i = 0; i < 4; i++)
                #pragma unroll
                for (int jj = 0; jj < 4; jj++)
                    O[i][jj] += p[i] * v[jj];
        }
    }

    // write y in [B,T,D] layout
    #pragma unroll
    for (int i = 0; i < 4; i++) {
        const float inv = 1.f / li[i];
        const int trow = m0 + ty * 4 + i;
        float* dst = y + ((size_t)(b * T_ + trow)) * D_ + h * DH_ + tx * 4;
        #pragma unroll
        for (int jj = 0; jj < 4; jj++) dst[jj] = O[i][jj] * inv;
    }
}

// ---------------------------------------------------------------------------
// act = silu(gate) * up, in place into gate
// ---------------------------------------------------------------------------
__global__ void act_kernel(float* __restrict__ gate, const float* __restrict__ up)
{
    const size_t i = (size_t)blockIdx.x * blockDim.x + threadIdx.x;  // float4
    float4 g = *(const float4*)(gate + i * 4);
    float4 u = *(const float4*)(up + i * 4);
    float4 o;
    o.x = g.x / (1.f + __expf(-g.x)) * u.x;
    o.y = g.y / (1.f + __expf(-g.y)) * u.y;
    o.z = g.z / (1.f + __expf(-g.z)) * u.z;
    o.w = g.w / (1.f + __expf(-g.w)) * u.w;
    *(float4*)(gate + i * 4) = o;
}

// ---------------------------------------------------------------------------
// Launch
// ---------------------------------------------------------------------------
extern "C" void kernel_launch(void* const* d_in, const int* in_sizes, int n_in,
                              void* d_out, int out_size)
{
    const float* x     = (const float*)d_in[0];
    const float* rc    = (const float*)d_in[1];
    const float* rs    = (const float*)d_in[2];
    const float* lerpw = (const float*)d_in[3];
    const float* lerpb = (const float*)d_in[4];
    const float* anw   = (const float*)d_in[5];
    const float* wqkv  = (const float*)d_in[6];
    const float* qnw   = (const float*)d_in[7];
    const float* knw   = (const float*)d_in[8];
    const float* qpb   = (const float*)d_in[9];
    const float* kpb   = (const float*)d_in[10];
    const float* ddw   = (const float*)d_in[11];
    const float* ddb   = (const float*)d_in[12];
    const float* wo    = (const float*)d_in[13];
    const float* mnw   = (const float*)d_in[14];
    const float* gw    = (const float*)d_in[15];
    const float* uw    = (const float*)d_in[16];
    const float* dw    = (const float*)d_in[17];
    float* out = (float*)d_out;

    float *glin, *xmix, *h, *qkv, *dd, *qt, *kt, *vt, *y, *x2, *gate, *up;
    cudaGetSymbolAddress((void**)&glin, s_glin);
    cudaGetSymbolAddress((void**)&xmix, s_xmix);
    cudaGetSymbolAddress((void**)&h,    s_h);
    cudaGetSymbolAddress((void**)&qkv,  s_qkv);
    cudaGetSymbolAddress((void**)&dd,   s_dd);
    cudaGetSymbolAddress((void**)&qt,   s_qt);
    cudaGetSymbolAddress((void**)&kt,   s_kt);
    cudaGetSymbolAddress((void**)&vt,   s_vt);
    cudaGetSymbolAddress((void**)&y,    s_y);
    cudaGetSymbolAddress((void**)&x2,   s_x2);
    cudaGetSymbolAddress((void**)&gate, s_gate);
    cudaGetSymbolAddress((void**)&up,   s_up);

    cudaFuncSetAttribute(flash_kernel,
                         cudaFuncAttributeMaxDynamicSharedMemorySize, 49152);

    const dim3 blk(256);

    // 1. glin = x @ lerp_w^T + lerp_b
    gemm64<<<dim3(D_ / 64, M_ / 64), blk>>>(x, lerpw, lerpb, nullptr, glin, D_, D_, 1);
    // 2. xmix = (1-sig(glin))*x + sig(glin)*x_prev
    mix_kernel<<<(M_ * D_ / 4) / 256, blk>>>(x, glin, xmix);
    // 3. h = rmsnorm(xmix) * attn_norm_w
    rmsnorm_kernel<<<M_, blk>>>(xmix, anw, h);
    // 4. qkv = h @ w_qkv^T
    gemm64<<<dim3(3 * D_ / 64, M_ / 64), blk>>>(h, wqkv, nullptr, nullptr, qkv, 3 * D_, D_, 0);
    // 5. dd = xmix @ dd_w^T + dd_b
    gemm64<<<dim3((NH_ * 16) / 64, M_ / 64), blk>>>(xmix, ddw, ddb, nullptr, dd, NH_ * 16, D_, 1);
    // 6. cumsum along T (in place)
    cumsum_kernel<<<B_, blk>>>(dd);
    // 7. q/k norm + hybrid rope + head-major scatter
    qkv_transform_kernel<<<(B_ * T_ * NH_) / 8, blk>>>(qkv, dd, rc, rs, qnw, knw,
                                                       qpb, kpb, qt, kt, vt);
    // 8. causal flash attention -> y [B,T,D]
    flash_kernel<<<dim3(T_ / 64, B_ * NH_), blk, 49152>>>(qt, kt, vt, y);
    // 9. x2 = xmix + y @ w_o^T
    gemm64<<<dim3(D_ / 64, M_ / 64), blk>>>(y, wo, nullptr, xmix, x2, D_, D_, 2);
    // 10. h = rmsnorm(x2) * mlp_norm_w
    rmsnorm_kernel<<<M_, blk>>>(x2, mnw, h);
    // 11/12. gate, up projections (N=2736 needs guard -> 43 col blocks)
    gemm64<<<dim3((FFN_ + 63) / 64, M_ / 64), blk>>>(h, gw, nullptr, nullptr, gate, FFN_, D_, 0);
    gemm64<<<dim3((FFN_ + 63) / 64, M_ / 64), blk>>>(h, uw, nullptr, nullptr, up, FFN_, D_, 0);
    // 13. act = silu(gate)*up
    act_kernel<<<(M_ * FFN_ / 4) / 256, blk>>>(gate, up);
    // 14. out = x2 + act @ down_w^T
    gemm64<<<dim3(D_ / 64, M_ / 64), blk>>>(gate, dw, nullptr, x2, out, D_, FFN_, 2);
}

// round 3
// speedup vs baseline: 1.8786x; 1.8786x over previous
#include <cuda_runtime.h>
#include <cuda_bf16.h>
#include <math.h>
#include <stdint.h>

// ---------------------------------------------------------------------------
// Problem constants
// ---------------------------------------------------------------------------
#define B_   2
#define T_   2048
#define D_   1024
#define NH_  16
#define DH_  64
#define FFN_ 2736
#define FFNP 2816                 // FFN padded to 128*22
#define M_   (B_ * T_)            // 4096 rows
#define EPS_ 1e-6f

// ---------------------------------------------------------------------------
// Arch-generic tensor-core PTX (sm_80+; valid under compute_103 target)
// ---------------------------------------------------------------------------
__device__ __forceinline__ uint32_t smem_u32(const void* p) {
    uint32_t a;
    asm("{ .reg .u64 t; cvta.to.shared.u64 t, %1; cvt.u32.u64 %0, t; }"
        : "=r"(a) : "l"(p));
    return a;
}
#define CP_ASYNC16(dst, src) \
    asm volatile("cp.async.cg.shared.global [%0], [%1], 16;" :: "r"(dst), "l"(src))
#define CP_COMMIT() asm volatile("cp.async.commit_group;" ::: "memory")
#define CP_WAIT0()  asm volatile("cp.async.wait_group 0;" ::: "memory")
#define CP_WAIT1()  asm volatile("cp.async.wait_group 1;" ::: "memory")
#define LDSM_X4(r0, r1, r2, r3, addr) \
    asm volatile("ldmatrix.sync.aligned.m8n8.x4.shared.b16 {%0,%1,%2,%3}, [%4];" \
                 : "=r"(r0), "=r"(r1), "=r"(r2), "=r"(r3) : "r"(addr))
#define MMA16816(d, a, b0, b1) \
    asm volatile("mma.sync.aligned.m16n8k16.row.col.f32.bf16.bf16.f32 " \
                 "{%0,%1,%2,%3},{%4,%5,%6,%7},{%8,%9},{%0,%1,%2,%3};" \
                 : "+f"((d)[0]), "+f"((d)[1]), "+f"((d)[2]), "+f"((d)[3]) \
                 : "r"((a)[0]), "r"((a)[1]), "r"((a)[2]), "r"((a)[3]), \
                   "r"(b0), "r"(b1))

// ---------------------------------------------------------------------------
// Device scratch
// ---------------------------------------------------------------------------
__device__ float s_glin[M_ * D_];
__device__ float s_xmix[M_ * D_];
__device__ float s_h   [M_ * D_];
__device__ float s_qkv [M_ * 3 * D_];
__device__ float s_dd  [M_ * NH_ * 16];
__device__ float s_qt  [B_ * NH_ * T_ * DH_];
__device__ float s_kt  [B_ * NH_ * T_ * DH_];
__device__ float s_vt  [B_ * NH_ * T_ * DH_];
__device__ float s_y   [M_ * D_];
__device__ float s_x2  [M_ * D_];
__device__ float s_gate[M_ * FFNP];
__device__ float s_up  [M_ * FFNP];
__device__ __nv_bfloat16 g_ah[(size_t)M_ * FFNP];
__device__ __nv_bfloat16 g_al[(size_t)M_ * FFNP];
__device__ __nv_bfloat16 g_wh[3 * D_ * D_];
__device__ __nv_bfloat16 g_wl[3 * D_ * D_];

// ---------------------------------------------------------------------------
// fp32 -> bf16 hi/lo split with 2D zero-padding
// ---------------------------------------------------------------------------
__global__ void convsplit(const float* __restrict__ src,
                          __nv_bfloat16* __restrict__ h,
                          __nv_bfloat16* __restrict__ l,
                          int rows, int cols, int rows_pad, int cols_pad)
{
    size_t i = (size_t)blockIdx.x * blockDim.x + threadIdx.x;
    size_t total = (size_t)rows_pad * cols_pad;
    if (i >= total) return;
    int r = (int)(i / cols_pad);
    int c = (int)(i - (size_t)r * cols_pad);
    float v = (r < rows && c < cols) ? src[(size_t)r * cols + c] : 0.f;
    __nv_bfloat16 hi = __float2bfloat16(v);
    float rr = v - __bfloat162float(hi);
    h[i] = hi;
    l[i] = __float2bfloat16(rr);
}

// ---------------------------------------------------------------------------
// mma.sync split-bf16 GEMM: C[M,N] = A[M,K] @ W[N,K]^T (+bias)(+res)
// CTA tile 128x128, BK=32, 8 warps (2x4), warp tile 64x32, double-buffered
// cp.async. smem rows padded to 80B -> conflict-free ldmatrix.
// ---------------------------------------------------------------------------
#define MATB 10240                        // bytes per matrix buffer (128*80)
#define BUFB (4 * MATB)                   // 40960 per stage

__global__ __launch_bounds__(256, 1) void mma_gemm(
    const __nv_bfloat16* __restrict__ Ah, const __nv_bfloat16* __restrict__ Al,
    const __nv_bfloat16* __restrict__ Wh, const __nv_bfloat16* __restrict__ Wl,
    const float* __restrict__ bias, const float* __restrict__ res,
    float* __restrict__ C, int K, int NKB, int ldc, int mode)
{
    extern __shared__ char smem[];
    const uint32_t su = smem_u32(smem);
    const int tid = threadIdx.x;
    const int wid = tid >> 5, lane = tid & 31;
    const int wm = wid >> 2, wn = wid & 3;     // warp grid 2 x 4
    const int m0 = blockIdx.y * 128, n0 = blockIdx.x * 128;

    // ldmatrix lane-dependent base offsets
    const uint32_t a_lrow = (uint32_t)(wm * 64 + (lane & 15)) * 80u + ((lane >> 4) * 16u);
    const uint32_t b_lrow = (uint32_t)(wn * 32 + ((lane >> 4) & 1) * 8 + (lane & 7)) * 80u
                          + (((lane >> 3) & 1) * 16u);

    float acc[4][4][4] = {};

    // async fill of stage b with K-chunk kb
    const int ch0 = tid * 2;
    #define LOAD_BUF(kb, b) do {                                              \
        _Pragma("unroll")                                                     \
        for (int c = 0; c < 2; c++) {                                         \
            const int ch = ch0 + c;                                           \
            const int row = ch >> 2, sub = ch & 3;                            \
            const uint32_t dst = su + (b) * BUFB + (uint32_t)row * 80u + sub * 16u; \
            const size_t asrc = (size_t)(m0 + row) * K + (kb) * 32 + sub * 8; \
            const size_t wsrc = (size_t)(n0 + row) * K + (kb) * 32 + sub * 8; \
            CP_ASYNC16(dst +        0, Ah + asrc);                            \
            CP_ASYNC16(dst +     MATB, Al + asrc);                            \
            CP_ASYNC16(dst + 2 * MATB, Wh + wsrc);                            \
            CP_ASYNC16(dst + 3 * MATB, Wl + wsrc);                            \
        }                                                                     \
    } while (0)

    LOAD_BUF(0, 0);
    CP_COMMIT();

    for (int kb = 0; kb < NKB; kb++) {
        if (kb + 1 < NKB) {
            LOAD_BUF(kb + 1, (kb + 1) & 1);
            CP_COMMIT();
            CP_WAIT1();
        } else {
            CP_WAIT0();
        }
        __syncthreads();

        const uint32_t sb = su + (kb & 1) * BUFB;
        #pragma unroll
        for (int ks = 0; ks < 2; ks++) {
            uint32_t ah[4][4], al[4][4];        // [mt][frag]
            uint32_t bh[2][4], bl[2][4];        // [np][frag]
            #pragma unroll
            for (int mt = 0; mt < 4; mt++) {
                const uint32_t ra = sb + a_lrow + (uint32_t)mt * 16u * 80u + ks * 32u;
                LDSM_X4(ah[mt][0], ah[mt][1], ah[mt][2], ah[mt][3], ra);
                LDSM_X4(al[mt][0], al[mt][1], al[mt][2], al[mt][3], ra + MATB);
            }
            #pragma unroll
            for (int np = 0; np < 2; np++) {
                const uint32_t rb = sb + 2 * MATB + b_lrow + (uint32_t)np * 16u * 80u + ks * 32u;
                LDSM_X4(bh[np][0], bh[np][1], bh[np][2], bh[np][3], rb);
                LDSM_X4(bl[np][0], bl[np][1], bl[np][2], bl[np][3], rb + MATB);
            }
            #pragma unroll
            for (int mt = 0; mt < 4; mt++)
                #pragma unroll
                for (int nt = 0; nt < 4; nt++) {
                    const int np = nt >> 1, o = (nt & 1) * 2;
                    MMA16816(acc[mt][nt], ah[mt], bh[np][o], bh[np][o + 1]);
                    MMA16816(acc[mt][nt], ah[mt], bl[np][o], bl[np][o + 1]);
                    MMA16816(acc[mt][nt], al[mt], bh[np][o], bh[np][o + 1]);
                }
        }
        __syncthreads();
    }

    // epilogue: direct float2 stores
    const int qrow = lane >> 2, qcol = (lane & 3) * 2;
    #pragma unroll
    for (int mt = 0; mt < 4; mt++) {
        const int r0 = m0 + wm * 64 + mt * 16 + qrow;
        #pragma unroll
        for (int nt = 0; nt < 4; nt++) {
            const int c0 = n0 + wn * 32 + nt * 8 + qcol;
            float bx = 0.f, by = 0.f;
            if (mode & 1) { bx = bias[c0]; by = bias[c0 + 1]; }
            float2 v0 = make_float2(acc[mt][nt][0] + bx, acc[mt][nt][1] + by);
            float2 v1 = make_float2(acc[mt][nt][2] + bx, acc[mt][nt][3] + by);
            const size_t i0 = (size_t)r0 * ldc + c0;
            const size_t i1 = (size_t)(r0 + 8) * ldc + c0;
            if (mode & 2) {
                float2 r0v = *(const float2*)(res + i0);
                float2 r1v = *(const float2*)(res + i1);
                v0.x += r0v.x; v0.y += r0v.y;
                v1.x += r1v.x; v1.y += r1v.y;
            }
            *(float2*)(C + i0) = v0;
            *(float2*)(C + i1) = v1;
        }
    }
    #undef LOAD_BUF
}

// ---------------------------------------------------------------------------
// elementwise / norm / scan / transform / attention (validated in R1)
// ---------------------------------------------------------------------------
__global__ void mix_kernel(const float* __restrict__ x,
                           const float* __restrict__ glin,
                           float* __restrict__ out)
{
    const size_t i = (size_t)blockIdx.x * blockDim.x + threadIdx.x;
    const int row = (int)(i >> 8);
    const int t = row & (T_ - 1);
    float4 xv = *(const float4*)(x + i * 4);
    float4 gv = *(const float4*)(glin + i * 4);
    float4 pv = make_float4(0.f, 0.f, 0.f, 0.f);
    if (t > 0) pv = *(const float4*)(x + (i - 256) * 4);
    float4 o; float g;
    g = 1.f / (1.f + __expf(-gv.x)); o.x = (1.f - g) * xv.x + g * pv.x;
    g = 1.f / (1.f + __expf(-gv.y)); o.y = (1.f - g) * xv.y + g * pv.y;
    g = 1.f / (1.f + __expf(-gv.z)); o.z = (1.f - g) * xv.z + g * pv.z;
    g = 1.f / (1.f + __expf(-gv.w)); o.w = (1.f - g) * xv.w + g * pv.w;
    *(float4*)(out + i * 4) = o;
}

__global__ __launch_bounds__(256) void rmsnorm_kernel(
    const float* __restrict__ x, const float* __restrict__ w,
    float* __restrict__ out)
{
    const int row = blockIdx.x;
    const int tid = threadIdx.x;
    const float* xr = x + (size_t)row * D_;
    float4 v = *(const float4*)(xr + tid * 4);
    float s = v.x * v.x + v.y * v.y + v.z * v.z + v.w * v.w;
    #pragma unroll
    for (int m = 16; m > 0; m >>= 1) s += __shfl_xor_sync(0xffffffffu, s, m);
    __shared__ float red[8];
    if ((tid & 31) == 0) red[tid >> 5] = s;
    __syncthreads();
    if (tid < 32) {
        float t = (tid < 8) ? red[tid] : 0.f;
        #pragma unroll
        for (int m = 4; m > 0; m >>= 1) t += __shfl_xor_sync(0xffffffffu, t, m);
        if (tid == 0) red[0] = t;
    }
    __syncthreads();
    const float inv = rsqrtf(red[0] / (float)D_ + EPS_);
    float4 wv = *(const float4*)(w + tid * 4);
    float4 o;
    o.x = v.x * inv * wv.x; o.y = v.y * inv * wv.y;
    o.z = v.z * inv * wv.z; o.w = v.w * inv * wv.w;
    *(float4*)(out + (size_t)row * D_ + tid * 4) = o;
}

__global__ void cumsum_kernel(float* __restrict__ dd)
{
    const int c = threadIdx.x;
    const int b = blockIdx.x;
    float acc = 0.f;
    size_t base = (size_t)b * T_ * 256 + c;
    #pragma unroll 8
    for (int t = 0; t < T_; t++) {
        acc += dd[base];
        dd[base] = acc;
        base += 256;
    }
}

__global__ __launch_bounds__(256) void qkv_transform_kernel(
    const float* __restrict__ qkv, const float* __restrict__ ddcum,
    const float* __restrict__ rc, const float* __restrict__ rs,
    const float* __restrict__ qnw, const float* __restrict__ knw,
    const float* __restrict__ qpb, const float* __restrict__ kpb,
    float* __restrict__ qt, float* __restrict__ kt, float* __restrict__ vt)
{
    const int w = blockIdx.x * 8 + (threadIdx.x >> 5);
    const int lane = threadIdx.x & 31;
    const int b = w >> 15;
    const int rem = w & 32767;
    const int t = rem >> 4;
    const int h = rem & 15;

    const size_t base = ((size_t)(b * T_ + t) * 3) * D_ + h * DH_;
    float q0 = qkv[base + lane],          q1 = qkv[base + 32 + lane];
    float k0 = qkv[base + D_ + lane],     k1 = qkv[base + D_ + 32 + lane];
    float v0 = qkv[base + 2 * D_ + lane], v1 = qkv[base + 2 * D_ + 32 + lane];

    float sq = q0 * q0 + q1 * q1;
    float sk = k0 * k0 + k1 * k1;
    #pragma unroll
    for (int m = 16; m > 0; m >>= 1) {
        sq += __shfl_xor_sync(0xffffffffu, sq, m);
        sk += __shfl_xor_sync(0xffffffffu, sk, m);
    }
    const float rq = rsqrtf(sq / 64.f + EPS_);
    const float rk = rsqrtf(sk / 64.f + EPS_);
    q0 *= rq * qnw[lane] * qpb[lane];
    q1 *= rq * qnw[lane + 32] * qpb[lane + 32];
    k0 *= rk * knw[lane] * kpb[lane];
    k1 *= rk * knw[lane + 32] * kpb[lane + 32];

    const int j = lane & 15;
    const float c = rc[t * 32 + j], s = rs[t * 32 + j];
    const float ang = ddcum[((size_t)(b * T_ + t)) * 256 + h * 16 + j];
    float s2, c2;
    sincosf(ang, &s2, &c2);

    const float qp0 = __shfl_xor_sync(0xffffffffu, q0, 16);
    const float qp1 = __shfl_xor_sync(0xffffffffu, q1, 16);
    const float kp0 = __shfl_xor_sync(0xffffffffu, k0, 16);
    const float kp1 = __shfl_xor_sync(0xffffffffu, k1, 16);
    float oq0, oq1, ok0, ok1;
    if (lane < 16) {
        oq0 = q0 * c - qp0 * s;  oq1 = q1 * c2 - qp1 * s2;
        ok0 = k0 * c - kp0 * s;  ok1 = k1 * c2 - kp1 * s2;
    } else {
        oq0 = q0 * c + qp0 * s;  oq1 = q1 * c2 + qp1 * s2;
        ok0 = k0 * c + kp0 * s;  ok1 = k1 * c2 + kp1 * s2;
    }

    const size_t ob = ((size_t)(b * NH_ + h) * T_ + t) * DH_;
    qt[ob + lane] = oq0;  qt[ob + 32 + lane] = oq1;
    kt[ob + lane] = ok0;  kt[ob + 32 + lane] = ok1;
    vt[ob + lane] = v0;   vt[ob + 32 + lane] = v1;
}

__global__ __launch_bounds__(256) void flash_kernel(
    const float* __restrict__ qt, const float* __restrict__ kt,
    const float* __restrict__ vt, float* __restrict__ y)
{
    extern __shared__ float fsm[];
    float* Qs  = fsm;
    float* KPs = fsm + 4096;
    float* Vs  = fsm + 8192;

    const int tid = threadIdx.x;
    const int tx = tid & 15, ty = tid >> 4;
    const int bx = blockIdx.x;
    const int bh = blockIdx.y;
    const int b = bh >> 4, h = bh & 15;
    const int m0 = bx * 64;
    const int lr = tid >> 2, ld0 = (tid & 3) << 4;

    const float* Qb = qt + (size_t)bh * T_ * DH_;
    const float* Kb = kt + (size_t)bh * T_ * DH_;
    const float* Vb = vt + (size_t)bh * T_ * DH_;

    {
        const float* src = Qb + (size_t)(m0 + lr) * DH_ + ld0;
        #pragma unroll
        for (int cch = 0; cch < 16; cch += 4) {
            float4 v = *(const float4*)(src + cch);
            Qs[(ld0 + cch + 0) * 64 + lr] = v.x * 0.125f;
            Qs[(ld0 + cch + 1) * 64 + lr] = v.y * 0.125f;
            Qs[(ld0 + cch + 2) * 64 + lr] = v.z * 0.125f;
            Qs[(ld0 + cch + 3) * 64 + lr] = v.w * 0.125f;
        }
    }

    float mi[4], li[4], O[4][4] = {};
    #pragma unroll
    for (int i = 0; i < 4; i++) { mi[i] = -1e30f; li[i] = 0.f; }

    for (int nt = 0; nt <= bx; nt++) {
        const int n0 = nt * 64;
        __syncthreads();
        {
            const float* ks = Kb + (size_t)(n0 + lr) * DH_ + ld0;
            const float* vs = Vb + (size_t)(n0 + lr) * DH_ + ld0;
            #pragma unroll
            for (int cch = 0; cch < 16; cch += 4) {
                float4 kv = *(const float4*)(ks + cch);
                KPs[(ld0 + cch + 0) * 64 + lr] = kv.x;
                KPs[(ld0 + cch + 1) * 64 + lr] = kv.y;
                KPs[(ld0 + cch + 2) * 64 + lr] = kv.z;
                KPs[(ld0 + cch + 3) * 64 + lr] = kv.w;
                *(float4*)&Vs[lr * 64 + ld0 + cch] = *(const float4*)(vs + cch);
            }
        }
        __syncthreads();

        float S[4][4] = {};
        #pragma unroll 8
        for (int d = 0; d < 64; d++) {
            float a[4], bb[4];
            *(float4*)a  = *(const float4*)&Qs[d * 64 + ty * 4];
            *(float4*)bb = *(const float4*)&KPs[d * 64 + tx * 4];
            #pragma unroll
            for (int i = 0; i < 4; i++)
                #pragma unroll
                for (int jj = 0; jj < 4; jj++)
                    S[i][jj] += a[i] * bb[jj];
        }
        if (nt == bx) {
            #pragma unroll
            for (int i = 0; i < 4; i++)
                #pragma unroll
                for (int jj = 0; jj < 4; jj++)
                    if (tx * 4 + jj > ty * 4 + i) S[i][jj] = -1e30f;
        }
        #pragma unroll
        for (int i = 0; i < 4; i++) {
            float mx = fmaxf(fmaxf(S[i][0], S[i][1]), fmaxf(S[i][2], S[i][3]));
            #pragma unroll
            for (int m = 1; m < 16; m <<= 1)
                mx = fmaxf(mx, __shfl_xor_sync(0xffffffffu, mx, m));
            const float mnew = fmaxf(mi[i], mx);
            const float corr = __expf(mi[i] - mnew);
            float rsum = 0.f;
            #pragma unroll
            for (int jj = 0; jj < 4; jj++) {
                S[i][jj] = __expf(S[i][jj] - mnew);
                rsum += S[i][jj];
            }
            #pragma unroll
            for (int m = 1; m < 16; m <<= 1)
                rsum += __shfl_xor_sync(0xffffffffu, rsum, m);
            li[i] = li[i] * corr + rsum;
            mi[i] = mnew;
            #pragma unroll
            for (int jj = 0; jj < 4; jj++) O[i][jj] *= corr;
        }
        __syncthreads();
        #pragma unroll
        for (int i = 0; i < 4; i++)
            #pragma unroll
            for (int jj = 0; jj < 4; jj++)
                KPs[(tx * 4 + jj) * 64 + ty * 4 + i] = S[i][jj];
        __syncthreads();
        #pragma unroll 8
        for (int n = 0; n < 64; n++) {
            float p[4], v[4];
            *(float4*)p = *(const float4*)&KPs[n * 64 + ty * 4];
            *(float4*)v = *(const float4*)&Vs[n * 64 + tx * 4];
            #pragma unroll
            for (int i = 0; i < 4; i++)
                #pragma unroll
                for (int jj = 0; jj < 4; jj++)
                    O[i][jj] += p[i] * v[jj];
        }
    }

    #pragma unroll
    for (int i = 0; i < 4; i++) {
        const float inv = 1.f / li[i];
        const int trow = m0 + ty * 4 + i;
        float* dst = y + ((size_t)(b * T_ + trow)) * D_ + h * DH_ + tx * 4;
        #pragma unroll
        for (int jj = 0; jj < 4; jj++) dst[jj] = O[i][jj] * inv;
    }
}

__global__ void act_kernel(float* __restrict__ gate, const float* __restrict__ up)
{
    const size_t i = (size_t)blockIdx.x * blockDim.x + threadIdx.x;
    float4 g = *(const float4*)(gate + i * 4);
    float4 u = *(const float4*)(up + i * 4);
    float4 o;
    o.x = g.x / (1.f + __expf(-g.x)) * u.x;
    o.y = g.y / (1.f + __expf(-g.y)) * u.y;
    o.z = g.z / (1.f + __expf(-g.z)) * u.z;
    o.w = g.w / (1.f + __expf(-g.w)) * u.w;
    *(float4*)(gate + i * 4) = o;
}

// ---------------------------------------------------------------------------
// Launch
// ---------------------------------------------------------------------------
static inline int cdiv(long long a, long long b) { return (int)((a + b - 1) / b); }

extern "C" void kernel_launch(void* const* d_in, const int* in_sizes, int n_in,
                              void* d_out, int out_size)
{
    const float* x     = (const float*)d_in[0];
    const float* rc    = (const float*)d_in[1];
    const float* rs    = (const float*)d_in[2];
    const float* lerpw = (const float*)d_in[3];
    const float* lerpb = (const float*)d_in[4];
    const float* anw   = (const float*)d_in[5];
    const float* wqkv  = (const float*)d_in[6];
    const float* qnw   = (const float*)d_in[7];
    const float* knw   = (const float*)d_in[8];
    const float* qpb   = (const float*)d_in[9];
    const float* kpb   = (const float*)d_in[10];
    const float* ddw   = (const float*)d_in[11];
    const float* ddb   = (const float*)d_in[12];
    const float* wo    = (const float*)d_in[13];
    const float* mnw   = (const float*)d_in[14];
    const float* gw    = (const float*)d_in[15];
    const float* uw    = (const float*)d_in[16];
    const float* dw    = (const float*)d_in[17];
    float* out = (float*)d_out;

    float *glin, *xmix, *h, *qkv, *dd, *qt, *kt, *vt, *y, *x2, *gate, *up;
    __nv_bfloat16 *ah, *al, *wh, *wl;
    cudaGetSymbolAddress((void**)&glin, s_glin);
    cudaGetSymbolAddress((void**)&xmix, s_xmix);
    cudaGetSymbolAddress((void**)&h,    s_h);
    cudaGetSymbolAddress((void**)&qkv,  s_qkv);
    cudaGetSymbolAddress((void**)&dd,   s_dd);
    cudaGetSymbolAddress((void**)&qt,   s_qt);
    cudaGetSymbolAddress((void**)&kt,   s_kt);
    cudaGetSymbolAddress((void**)&vt,   s_vt);
    cudaGetSymbolAddress((void**)&y,    s_y);
    cudaGetSymbolAddress((void**)&x2,   s_x2);
    cudaGetSymbolAddress((void**)&gate, s_gate);
    cudaGetSymbolAddress((void**)&up,   s_up);
    cudaGetSymbolAddress((void**)&ah,   g_ah);
    cudaGetSymbolAddress((void**)&al,   g_al);
    cudaGetSymbolAddress((void**)&wh,   g_wh);
    cudaGetSymbolAddress((void**)&wl,   g_wl);

    cudaFuncSetAttribute(flash_kernel,
                         cudaFuncAttributeMaxDynamicSharedMemorySize, 49152);
    cudaFuncSetAttribute(mma_gemm,
                         cudaFuncAttributeMaxDynamicSharedMemorySize, 2 * BUFB);

    const dim3 blk(256);
    const int GSM = 2 * BUFB;   // 81920

    #define CONV(src, dh, dl, r, c, rp, cp) \
        convsplit<<<cdiv((long long)(rp) * (cp), 256), blk>>>(src, dh, dl, r, c, rp, cp)

    // 1. glin = x @ lerp_w^T + lerp_b
    CONV(x, ah, al, M_, D_, M_, D_);
    CONV(lerpw, wh, wl, D_, D_, D_, D_);
    mma_gemm<<<dim3(8, 32), blk, GSM>>>(ah, al, wh, wl, lerpb, nullptr, glin, D_, 32, D_, 1);
    // 2. xmix
    mix_kernel<<<(M_ * D_ / 4) / 256, blk>>>(x, glin, xmix);
    // 3. h = rmsnorm(xmix)
    rmsnorm_kernel<<<M_, blk>>>(xmix, anw, h);
    // 4. qkv = h @ w_qkv^T
    CONV(h, ah, al, M_, D_, M_, D_);
    CONV(wqkv, wh, wl, 3 * D_, D_, 3 * D_, D_);
    mma_gemm<<<dim3(24, 32), blk, GSM>>>(ah, al, wh, wl, nullptr, nullptr, qkv, D_, 32, 3 * D_, 0);
    // 5. dd = xmix @ dd_w^T + dd_b
    CONV(xmix, ah, al, M_, D_, M_, D_);
    CONV(ddw, wh, wl, 256, D_, 256, D_);
    mma_gemm<<<dim3(2, 32), blk, GSM>>>(ah, al, wh, wl, ddb, nullptr, dd, D_, 32, 256, 1);
    // 6. cumsum
    cumsum_kernel<<<B_, blk>>>(dd);
    // 7. q/k transform
    qkv_transform_kernel<<<(B_ * T_ * NH_) / 8, blk>>>(qkv, dd, rc, rs, qnw, knw,
                                                       qpb, kpb, qt, kt, vt);
    // 8. flash attention
    flash_kernel<<<dim3(T_ / 64, B_ * NH_), blk, 49152>>>(qt, kt, vt, y);
    // 9. x2 = xmix + y @ w_o^T
    CONV(y, ah, al, M_, D_, M_, D_);
    CONV(wo, wh, wl, D_, D_, D_, D_);
    mma_gemm<<<dim3(8, 32), blk, GSM>>>(ah, al, wh, wl, nullptr, xmix, x2, D_, 32, D_, 2);
    // 10. h = rmsnorm(x2)
    rmsnorm_kernel<<<M_, blk>>>(x2, mnw, h);
    // 11/12. gate, up (N padded to 2816; pad rows of W are zero)
    CONV(h, ah, al, M_, D_, M_, D_);
    CONV(gw, wh, wl, FFN_, D_, FFNP, D_);
    mma_gemm<<<dim3(22, 32), blk, GSM>>>(ah, al, wh, wl, nullptr, nullptr, gate, D_, 32, FFNP, 0);
    CONV(uw, wh, wl, FFN_, D_, FFNP, D_);
    mma_gemm<<<dim3(22, 32), blk, GSM>>>(ah, al, wh, wl, nullptr, nullptr, up, D_, 32, FFNP, 0);
    // 13. act = silu(gate)*up  (padded cols: up=0 -> act=0)
    act_kernel<<<(M_ * FFNP / 4) / 256, blk>>>(gate, up);
    // 14. out = x2 + act @ down_w^T  (K = FFNP, pad cols zero)
    CONV(gate, ah, al, M_, FFNP, M_, FFNP);
    CONV(dw, wh, wl, D_, FFN_, D_, FFNP);
    mma_gemm<<<dim3(8, 32), blk, GSM>>>(ah, al, wh, wl, nullptr, x2, out, FFNP, 88, D_, 2);
}

// round 4
// speedup vs baseline: 2.5648x; 1.3653x over previous
#include <cuda_runtime.h>
#include <cuda_bf16.h>
#include <math.h>
#include <stdint.h>

// ---------------------------------------------------------------------------
// Problem constants
// ---------------------------------------------------------------------------
#define B_   2
#define T_   2048
#define D_   1024
#define NH_  16
#define DH_  64
#define FFN_ 2736
#define FFNP 2816
#define M_   (B_ * T_)
#define EPS_ 1e-6f

// ---------------------------------------------------------------------------
// PTX helpers (arch-generic, sm_80+)
// ---------------------------------------------------------------------------
__device__ __forceinline__ uint32_t smem_u32(const void* p) {
    uint32_t a;
    asm("{ .reg .u64 t; cvta.to.shared.u64 t, %1; cvt.u32.u64 %0, t; }"
        : "=r"(a) : "l"(p));
    return a;
}
#define CP_ASYNC16(dst, src) \
    asm volatile("cp.async.cg.shared.global [%0], [%1], 16;" :: "r"(dst), "l"(src))
#define CP_COMMIT() asm volatile("cp.async.commit_group;" ::: "memory")
#define CP_WAIT0()  asm volatile("cp.async.wait_group 0;" ::: "memory")
#define CP_WAIT1()  asm volatile("cp.async.wait_group 1;" ::: "memory")
#define LDSM_X4(r0, r1, r2, r3, addr) \
    asm volatile("ldmatrix.sync.aligned.m8n8.x4.shared.b16 {%0,%1,%2,%3}, [%4];" \
                 : "=r"(r0), "=r"(r1), "=r"(r2), "=r"(r3) : "r"(addr))
#define MMA16816(d, a, b0, b1) \
    asm volatile("mma.sync.aligned.m16n8k16.row.col.f32.bf16.bf16.f32 " \
                 "{%0,%1,%2,%3},{%4,%5,%6,%7},{%8,%9},{%0,%1,%2,%3};" \
                 : "+f"((d)[0]), "+f"((d)[1]), "+f"((d)[2]), "+f"((d)[3]) \
                 : "r"((a)[0]), "r"((a)[1]), "r"((a)[2]), "r"((a)[3]), \
                   "r"(b0), "r"(b1))
#define MMATF32(d, a, b0, b1) \
    asm volatile("mma.sync.aligned.m16n8k8.row.col.f32.tf32.tf32.f32 " \
                 "{%0,%1,%2,%3},{%4,%5,%6,%7},{%8,%9},{%0,%1,%2,%3};" \
                 : "+f"((d)[0]), "+f"((d)[1]), "+f"((d)[2]), "+f"((d)[3]) \
                 : "r"((a)[0]), "r"((a)[1]), "r"((a)[2]), "r"((a)[3]), \
                   "r"(b0), "r"(b1))
__device__ __forceinline__ uint32_t f2tf(float f) {
    uint32_t r;
    asm("cvt.rna.tf32.f32 %0, %1;" : "=r"(r) : "f"(f));
    return r;
}

// ---------------------------------------------------------------------------
// Device scratch
// ---------------------------------------------------------------------------
__device__ float s_glin[M_ * D_];
__device__ float s_xmix[M_ * D_];
__device__ float s_qkv [M_ * 3 * D_];
__device__ float s_dd  [M_ * NH_ * 16];
__device__ float s_csum[B_ * 16 * 256];
__device__ float s_qt  [B_ * NH_ * T_ * DH_];
__device__ float s_kt  [B_ * NH_ * T_ * DH_];
__device__ float s_vt  [B_ * NH_ * T_ * DH_];
__device__ float s_x2  [M_ * D_];
__device__ float s_gate[M_ * FFNP];
__device__ float s_up  [M_ * FFNP];
__device__ __nv_bfloat16 g_ah[(size_t)M_ * FFNP];
__device__ __nv_bfloat16 g_al[(size_t)M_ * FFNP];
__device__ __nv_bfloat16 g_wh[3 * D_ * D_];
__device__ __nv_bfloat16 g_wl[3 * D_ * D_];

// ---------------------------------------------------------------------------
// fp32 -> bf16 hi/lo split with 2D zero-padding (weights + x)
// ---------------------------------------------------------------------------
__global__ void convsplit(const float* __restrict__ src,
                          __nv_bfloat16* __restrict__ h,
                          __nv_bfloat16* __restrict__ l,
                          int rows, int cols, int rows_pad, int cols_pad)
{
    size_t i = (size_t)blockIdx.x * blockDim.x + threadIdx.x;
    size_t total = (size_t)rows_pad * cols_pad;
    if (i >= total) return;
    int r = (int)(i / cols_pad);
    int c = (int)(i - (size_t)r * cols_pad);
    float v = (r < rows && c < cols) ? src[(size_t)r * cols + c] : 0.f;
    __nv_bfloat16 hi = __float2bfloat16(v);
    h[i] = hi;
    l[i] = __float2bfloat16(v - __bfloat162float(hi));
}

// ---------------------------------------------------------------------------
// mma.sync split-bf16 GEMM (as validated in R3)
// ---------------------------------------------------------------------------
#define MATB 10240
#define BUFB (4 * MATB)

__global__ __launch_bounds__(256, 1) void mma_gemm(
    const __nv_bfloat16* __restrict__ Ah, const __nv_bfloat16* __restrict__ Al,
    const __nv_bfloat16* __restrict__ Wh, const __nv_bfloat16* __restrict__ Wl,
    const float* __restrict__ bias, const float* __restrict__ res,
    float* __restrict__ C, int K, int NKB, int ldc, int mode)
{
    extern __shared__ char smem[];
    const uint32_t su = smem_u32(smem);
    const int tid = threadIdx.x;
    const int wid = tid >> 5, lane = tid & 31;
    const int wm = wid >> 2, wn = wid & 3;
    const int m0 = blockIdx.y * 128, n0 = blockIdx.x * 128;

    const uint32_t a_lrow = (uint32_t)(wm * 64 + (lane & 15)) * 80u + ((lane >> 4) * 16u);
    const uint32_t b_lrow = (uint32_t)(wn * 32 + ((lane >> 4) & 1) * 8 + (lane & 7)) * 80u
                          + (((lane >> 3) & 1) * 16u);

    float acc[4][4][4] = {};

    const int ch0 = tid * 2;
    #define LOAD_BUF(kb, b) do {                                              \
        _Pragma("unroll")                                                     \
        for (int c = 0; c < 2; c++) {                                         \
            const int ch = ch0 + c;                                           \
            const int row = ch >> 2, sub = ch & 3;                            \
            const uint32_t dst = su + (b) * BUFB + (uint32_t)row * 80u + sub * 16u; \
            const size_t asrc = (size_t)(m0 + row) * K + (kb) * 32 + sub * 8; \
            const size_t wsrc = (size_t)(n0 + row) * K + (kb) * 32 + sub * 8; \
            CP_ASYNC16(dst +        0, Ah + asrc);                            \
            CP_ASYNC16(dst +     MATB, Al + asrc);                            \
            CP_ASYNC16(dst + 2 * MATB, Wh + wsrc);                            \
            CP_ASYNC16(dst + 3 * MATB, Wl + wsrc);                            \
        }                                                                     \
    } while (0)

    LOAD_BUF(0, 0);
    CP_COMMIT();

    for (int kb = 0; kb < NKB; kb++) {
        if (kb + 1 < NKB) {
            LOAD_BUF(kb + 1, (kb + 1) & 1);
            CP_COMMIT();
            CP_WAIT1();
        } else {
            CP_WAIT0();
        }
        __syncthreads();

        const uint32_t sb = su + (kb & 1) * BUFB;
        #pragma unroll
        for (int ks = 0; ks < 2; ks++) {
            uint32_t ah[4][4], al[4][4];
            uint32_t bh[2][4], bl[2][4];
            #pragma unroll
            for (int mt = 0; mt < 4; mt++) {
                const uint32_t ra = sb + a_lrow + (uint32_t)mt * 16u * 80u + ks * 32u;
                LDSM_X4(ah[mt][0], ah[mt][1], ah[mt][2], ah[mt][3], ra);
                LDSM_X4(al[mt][0], al[mt][1], al[mt][2], al[mt][3], ra + MATB);
            }
            #pragma unroll
            for (int np = 0; np < 2; np++) {
                const uint32_t rb = sb + 2 * MATB + b_lrow + (uint32_t)np * 16u * 80u + ks * 32u;
                LDSM_X4(bh[np][0], bh[np][1], bh[np][2], bh[np][3], rb);
                LDSM_X4(bl[np][0], bl[np][1], bl[np][2], bl[np][3], rb + MATB);
            }
            #pragma unroll
            for (int mt = 0; mt < 4; mt++)
                #pragma unroll
                for (int nt = 0; nt < 4; nt++) {
                    const int np = nt >> 1, o = (nt & 1) * 2;
                    MMA16816(acc[mt][nt], ah[mt], bh[np][o], bh[np][o + 1]);
                    MMA16816(acc[mt][nt], ah[mt], bl[np][o], bl[np][o + 1]);
                    MMA16816(acc[mt][nt], al[mt], bh[np][o], bh[np][o + 1]);
                }
        }
        __syncthreads();
    }

    const int qrow = lane >> 2, qcol = (lane & 3) * 2;
    #pragma unroll
    for (int mt = 0; mt < 4; mt++) {
        const int r0 = m0 + wm * 64 + mt * 16 + qrow;
        #pragma unroll
        for (int nt = 0; nt < 4; nt++) {
            const int c0 = n0 + wn * 32 + nt * 8 + qcol;
            float bx = 0.f, by = 0.f;
            if (mode & 1) { bx = bias[c0]; by = bias[c0 + 1]; }
            float2 v0 = make_float2(acc[mt][nt][0] + bx, acc[mt][nt][1] + by);
            float2 v1 = make_float2(acc[mt][nt][2] + bx, acc[mt][nt][3] + by);
            const size_t i0 = (size_t)r0 * ldc + c0;
            const size_t i1 = (size_t)(r0 + 8) * ldc + c0;
            if (mode & 2) {
                float2 r0v = *(const float2*)(res + i0);
                float2 r1v = *(const float2*)(res + i1);
                v0.x += r0v.x; v0.y += r0v.y;
                v1.x += r1v.x; v1.y += r1v.y;
            }
            *(float2*)(C + i0) = v0;
            *(float2*)(C + i1) = v1;
        }
    }
    #undef LOAD_BUF
}

// ---------------------------------------------------------------------------
// mix: xmix fp32 + bf16 hi/lo split fused
// ---------------------------------------------------------------------------
__global__ void mix_split_kernel(const float* __restrict__ x,
                                 const float* __restrict__ glin,
                                 float* __restrict__ xmix,
                                 __nv_bfloat16* __restrict__ oh,
                                 __nv_bfloat16* __restrict__ ol)
{
    const size_t i = (size_t)blockIdx.x * blockDim.x + threadIdx.x;
    const int row = (int)(i >> 8);
    const int t = row & (T_ - 1);
    float4 xv = *(const float4*)(x + i * 4);
    float4 gv = *(const float4*)(glin + i * 4);
    float4 pv = make_float4(0.f, 0.f, 0.f, 0.f);
    if (t > 0) pv = *(const float4*)(x + (i - 256) * 4);
    float o[4]; float g;
    g = 1.f / (1.f + __expf(-gv.x)); o[0] = (1.f - g) * xv.x + g * pv.x;
    g = 1.f / (1.f + __expf(-gv.y)); o[1] = (1.f - g) * xv.y + g * pv.y;
    g = 1.f / (1.f + __expf(-gv.z)); o[2] = (1.f - g) * xv.z + g * pv.z;
    g = 1.f / (1.f + __expf(-gv.w)); o[3] = (1.f - g) * xv.w + g * pv.w;
    *(float4*)(xmix + i * 4) = make_float4(o[0], o[1], o[2], o[3]);
    __nv_bfloat16 hb[4], lb[4];
    #pragma unroll
    for (int j = 0; j < 4; j++) {
        hb[j] = __float2bfloat16(o[j]);
        lb[j] = __float2bfloat16(o[j] - __bfloat162float(hb[j]));
    }
    *(uint2*)(oh + i * 4) = *(uint2*)hb;
    *(uint2*)(ol + i * 4) = *(uint2*)lb;
}

// ---------------------------------------------------------------------------
// RMSNorm fused with bf16 hi/lo split output
// ---------------------------------------------------------------------------
__global__ __launch_bounds__(256) void rmsnorm_split_kernel(
    const float* __restrict__ x, const float* __restrict__ w,
    __nv_bfloat16* __restrict__ oh, __nv_bfloat16* __restrict__ ol)
{
    const int row = blockIdx.x;
    const int tid = threadIdx.x;
    const float* xr = x + (size_t)row * D_;
    float4 v = *(const float4*)(xr + tid * 4);
    float s = v.x * v.x + v.y * v.y + v.z * v.z + v.w * v.w;
    #pragma unroll
    for (int m = 16; m > 0; m >>= 1) s += __shfl_xor_sync(0xffffffffu, s, m);
    __shared__ float red[8];
    if ((tid & 31) == 0) red[tid >> 5] = s;
    __syncthreads();
    if (tid < 32) {
        float t = (tid < 8) ? red[tid] : 0.f;
        #pragma unroll
        for (int m = 4; m > 0; m >>= 1) t += __shfl_xor_sync(0xffffffffu, t, m);
        if (tid == 0) red[0] = t;
    }
    __syncthreads();
    const float inv = rsqrtf(red[0] / (float)D_ + EPS_);
    float4 wv = *(const float4*)(w + tid * 4);
    float o[4] = { v.x * inv * wv.x, v.y * inv * wv.y,
                   v.z * inv * wv.z, v.w * inv * wv.w };
    __nv_bfloat16 hb[4], lb[4];
    #pragma unroll
    for (int j = 0; j < 4; j++) {
        hb[j] = __float2bfloat16(o[j]);
        lb[j] = __float2bfloat16(o[j] - __bfloat162float(hb[j]));
    }
    const size_t idx = (size_t)row * D_ + tid * 4;
    *(uint2*)(oh + idx) = *(uint2*)hb;
    *(uint2*)(ol + idx) = *(uint2*)lb;
}

// ---------------------------------------------------------------------------
// 3-phase cumsum over T per (b, channel)
// ---------------------------------------------------------------------------
__global__ void cumsumA(const float* __restrict__ dd, float* __restrict__ cs)
{
    const int c = threadIdx.x;
    const int blk = blockIdx.x;           // b*16 + chunk
    const int b = blk >> 4, ch = blk & 15;
    size_t base = ((size_t)b * T_ + ch * 128) * 256 + c;
    float s = 0.f;
    #pragma unroll 8
    for (int t = 0; t < 128; t++) { s += dd[base]; base += 256; }
    cs[(size_t)blk * 256 + c] = s;
}
__global__ void cumsumB(float* __restrict__ cs)
{
    const int c = threadIdx.x;
    const int b = blockIdx.x;
    float run = 0.f;
    #pragma unroll
    for (int ch = 0; ch < 16; ch++) {
        size_t i = ((size_t)b * 16 + ch) * 256 + c;
        float t = cs[i];
        cs[i] = run;
        run += t;
    }
}
__global__ void cumsumC(float* __restrict__ dd, const float* __restrict__ cs)
{
    const int c = threadIdx.x;
    const int blk = blockIdx.x;
    const int b = blk >> 4, ch = blk & 15;
    float acc = cs[(size_t)blk * 256 + c];
    size_t base = ((size_t)b * T_ + ch * 128) * 256 + c;
    #pragma unroll 8
    for (int t = 0; t < 128; t++) { acc += dd[base]; dd[base] = acc; base += 256; }
}

// ---------------------------------------------------------------------------
// q/k head rmsnorm + hybrid rope + head-major scatter
// ---------------------------------------------------------------------------
__global__ __launch_bounds__(256) void qkv_transform_kernel(
    const float* __restrict__ qkv, const float* __restrict__ ddcum,
    const float* __restrict__ rc, const float* __restrict__ rs,
    const float* __restrict__ qnw, const float* __restrict__ knw,
    const float* __restrict__ qpb, const float* __restrict__ kpb,
    float* __restrict__ qt, float* __restrict__ kt, float* __restrict__ vt)
{
    const int w = blockIdx.x * 8 + (threadIdx.x >> 5);
    const int lane = threadIdx.x & 31;
    const int b = w >> 15;
    const int rem = w & 32767;
    const int t = rem >> 4;
    const int h = rem & 15;

    const size_t base = ((size_t)(b * T_ + t) * 3) * D_ + h * DH_;
    float q0 = qkv[base + lane],          q1 = qkv[base + 32 + lane];
    float k0 = qkv[base + D_ + lane],     k1 = qkv[base + D_ + 32 + lane];
    float v0 = qkv[base + 2 * D_ + lane], v1 = qkv[base + 2 * D_ + 32 + lane];

    float sq = q0 * q0 + q1 * q1;
    float sk = k0 * k0 + k1 * k1;
    #pragma unroll
    for (int m = 16; m > 0; m >>= 1) {
        sq += __shfl_xor_sync(0xffffffffu, sq, m);
        sk += __shfl_xor_sync(0xffffffffu, sk, m);
    }
    const float rq = rsqrtf(sq / 64.f + EPS_);
    const float rk = rsqrtf(sk / 64.f + EPS_);
    q0 *= rq * qnw[lane] * qpb[lane];
    q1 *= rq * qnw[lane + 32] * qpb[lane + 32];
    k0 *= rk * knw[lane] * kpb[lane];
    k1 *= rk * knw[lane + 32] * kpb[lane + 32];

    const int j = lane & 15;
    const float c = rc[t * 32 + j], s = rs[t * 32 + j];
    const float ang = ddcum[((size_t)(b * T_ + t)) * 256 + h * 16 + j];
    float s2, c2;
    sincosf(ang, &s2, &c2);

    const float qp0 = __shfl_xor_sync(0xffffffffu, q0, 16);
    const float qp1 = __shfl_xor_sync(0xffffffffu, q1, 16);
    const float kp0 = __shfl_xor_sync(0xffffffffu, k0, 16);
    const float kp1 = __shfl_xor_sync(0xffffffffu, k1, 16);
    float oq0, oq1, ok0, ok1;
    if (lane < 16) {
        oq0 = q0 * c - qp0 * s;  oq1 = q1 * c2 - qp1 * s2;
        ok0 = k0 * c - kp0 * s;  ok1 = k1 * c2 - kp1 * s2;
    } else {
        oq0 = q0 * c + qp0 * s;  oq1 = q1 * c2 + qp1 * s2;
        ok0 = k0 * c + kp0 * s;  ok1 = k1 * c2 + kp1 * s2;
    }

    const size_t ob = ((size_t)(b * NH_ + h) * T_ + t) * DH_;
    qt[ob + lane] = oq0;  qt[ob + 32 + lane] = oq1;
    kt[ob + lane] = ok0;  kt[ob + 32 + lane] = ok1;
    vt[ob + lane] = v0;   vt[ob + 32 + lane] = v1;
}

// ---------------------------------------------------------------------------
// Flash attention with tf32 mma.sync.
// Q tile 128, K tile 64, 8 warps (16 query rows each).
// Smem: Ks[64][72] (tf32, [dim][key]), Vs[64][72] (tf32, [key][dim]),
//       Ps[128][68] (tf32, [row][key], warp-private rows).
// Output: bf16 hi/lo split of y, written in [B,T,D] layout.
// ---------------------------------------------------------------------------
#define KS_OFF 0
#define VS_OFF (64 * 72)
#define PS_OFF (2 * 64 * 72)
#define FSMEM ((2 * 64 * 72 + 128 * 68) * 4)

__global__ __launch_bounds__(256, 1) void flash_tc(
    const float* __restrict__ qt, const float* __restrict__ kt,
    const float* __restrict__ vt,
    __nv_bfloat16* __restrict__ yh, __nv_bfloat16* __restrict__ yl)
{
    extern __shared__ uint32_t fsm[];
    uint32_t* Ks = fsm + KS_OFF;
    uint32_t* Vs = fsm + VS_OFF;
    uint32_t* Ps = fsm + PS_OFF;

    const int tid = threadIdx.x, lane = tid & 31, w = tid >> 5;
    const int bx = blockIdx.x, bh = blockIdx.y;
    const int b = bh >> 4, h = bh & 15;
    const int m0 = bx * 128;

    const float* Qb = qt + (size_t)bh * T_ * DH_;
    const float* Kb = kt + (size_t)bh * T_ * DH_;
    const float* Vb = vt + (size_t)bh * T_ * DH_;

    // Q fragments (tf32), loaded once. rows r1, r1+8
    const int r1 = m0 + w * 16 + (lane >> 2);
    uint32_t qf[8][4];
    {
        const float* q1 = Qb + (size_t)r1 * DH_;
        const float* q2 = q1 + 8 * DH_;
        #pragma unroll
        for (int k8 = 0; k8 < 8; k8++) {
            const int c = k8 * 8 + (lane & 3);
            qf[k8][0] = f2tf(q1[c] * 0.125f);
            qf[k8][1] = f2tf(q2[c] * 0.125f);
            qf[k8][2] = f2tf(q1[c + 4] * 0.125f);
            qf[k8][3] = f2tf(q2[c + 4] * 0.125f);
        }
    }

    float mi[2] = { -1e30f, -1e30f }, li[2] = { 0.f, 0.f };
    float O[8][4] = {};

    const int ntiles = 2 * bx + 2;
    for (int nt = 0; nt < ntiles; nt++) {
        const int n0 = nt * 64;
        __syncthreads();
        // load K,V tile (tf32-converted)
        {
            const int key = tid >> 2, db = (tid & 3) * 16;
            const float* kp = Kb + (size_t)(n0 + key) * DH_ + db;
            const float* vp = Vb + (size_t)(n0 + key) * DH_ + db;
            #pragma unroll
            for (int i = 0; i < 16; i += 4) {
                float4 kv = *(const float4*)(kp + i);
                Ks[(db + i + 0) * 72 + key] = f2tf(kv.x);
                Ks[(db + i + 1) * 72 + key] = f2tf(kv.y);
                Ks[(db + i + 2) * 72 + key] = f2tf(kv.z);
                Ks[(db + i + 3) * 72 + key] = f2tf(kv.w);
                float4 vv = *(const float4*)(vp + i);
                uint4 vo;
                vo.x = f2tf(vv.x); vo.y = f2tf(vv.y);
                vo.z = f2tf(vv.z); vo.w = f2tf(vv.w);
                *(uint4*)&Vs[key * 72 + db + i] = vo;
            }
        }
        __syncthreads();

        // S = Q K^T
        float S[8][4] = {};
        #pragma unroll
        for (int k8 = 0; k8 < 8; k8++) {
            const uint32_t* kr0 = &Ks[(k8 * 8 + (lane & 3)) * 72 + (lane >> 2)];
            const uint32_t* kr1 = kr0 + 4 * 72;
            #pragma unroll
            for (int n8 = 0; n8 < 8; n8++) {
                MMATF32(S[n8], qf[k8], kr0[n8 * 8], kr1[n8 * 8]);
            }
        }
        // causal mask on diagonal tiles
        if (nt >= 2 * bx) {
            #pragma unroll
            for (int n8 = 0; n8 < 8; n8++) {
                const int cb = n0 + n8 * 8 + 2 * (lane & 3);
                if (cb     > r1)     S[n8][0] = -1e30f;
                if (cb + 1 > r1)     S[n8][1] = -1e30f;
                if (cb     > r1 + 8) S[n8][2] = -1e30f;
                if (cb + 1 > r1 + 8) S[n8][3] = -1e30f;
            }
        }
        // online softmax (rows r1, r1+8). quad lanes share a row.
        #pragma unroll
        for (int half = 0; half < 2; half++) {
            float mx = -1e30f;
            #pragma unroll
            for (int n8 = 0; n8 < 8; n8++)
                mx = fmaxf(mx, fmaxf(S[n8][half * 2], S[n8][half * 2 + 1]));
            mx = fmaxf(mx, __shfl_xor_sync(0xffffffffu, mx, 1));
            mx = fmaxf(mx, __shfl_xor_sync(0xffffffffu, mx, 2));
            const float mnew = fmaxf(mi[half], mx);
            const float corr = __expf(mi[half] - mnew);
            float rsum = 0.f;
            #pragma unroll
            for (int n8 = 0; n8 < 8; n8++) {
                float e0 = __expf(S[n8][half * 2]     - mnew);
                float e1 = __expf(S[n8][half * 2 + 1] - mnew);
                S[n8][half * 2] = e0; S[n8][half * 2 + 1] = e1;
                rsum += e0 + e1;
            }
            rsum += __shfl_xor_sync(0xffffffffu, rsum, 1);
            rsum += __shfl_xor_sync(0xffffffffu, rsum, 2);
            li[half] = li[half] * corr + rsum;
            mi[half] = mnew;
            #pragma unroll
            for (int n8 = 0; n8 < 8; n8++) {
                O[n8][half * 2]     *= corr;
                O[n8][half * 2 + 1] *= corr;
            }
        }
        // write P (tf32) to warp-private Ps rows
        {
            const int pr = w * 16 + (lane >> 2);
            #pragma unroll
            for (int n8 = 0; n8 < 8; n8++) {
                const int pc = n8 * 8 + 2 * (lane & 3);
                uint2 p0, p1;
                p0.x = f2tf(S[n8][0]); p0.y = f2tf(S[n8][1]);
                p1.x = f2tf(S[n8][2]); p1.y = f2tf(S[n8][3]);
                *(uint2*)&Ps[pr * 68 + pc]       = p0;
                *(uint2*)&Ps[(pr + 8) * 68 + pc] = p1;
            }
        }
        __syncwarp();
        // O += P V
        #pragma unroll
        for (int k8 = 0; k8 < 8; k8++) {
            uint32_t a[4];
            const int pr = w * 16 + (lane >> 2);
            const int pc = k8 * 8 + (lane & 3);
            a[0] = Ps[pr * 68 + pc];
            a[1] = Ps[(pr + 8) * 68 + pc];
            a[2] = Ps[pr * 68 + pc + 4];
            a[3] = Ps[(pr + 8) * 68 + pc + 4];
            const uint32_t* vr0 = &Vs[(k8 * 8 + (lane & 3)) * 72 + (lane >> 2)];
            const uint32_t* vr1 = vr0 + 4 * 72;
            #pragma unroll
            for (int n8 = 0; n8 < 8; n8++) {
                MMATF32(O[n8], a, vr0[n8 * 8], vr1[n8 * 8]);
            }
        }
    }

    // epilogue: normalize + bf16 hi/lo split write
    const float inv0 = 1.f / li[0], inv1 = 1.f / li[1];
    const size_t o1 = ((size_t)(b * T_ + r1)) * D_ + h * DH_ + 2 * (lane & 3);
    const size_t o2 = o1 + 8 * D_;
    #pragma unroll
    for (int n8 = 0; n8 < 8; n8++) {
        float v0 = O[n8][0] * inv0, v1 = O[n8][1] * inv0;
        float v2 = O[n8][2] * inv1, v3 = O[n8][3] * inv1;
        __nv_bfloat162 h0, h1, l0, l1;
        h0.x = __float2bfloat16(v0); h0.y = __float2bfloat16(v1);
        h1.x = __float2bfloat16(v2); h1.y = __float2bfloat16(v3);
        l0.x = __float2bfloat16(v0 - __bfloat162float(h0.x));
        l0.y = __float2bfloat16(v1 - __bfloat162float(h0.y));
        l1.x = __float2bfloat16(v2 - __bfloat162float(h1.x));
        l1.y = __float2bfloat16(v3 - __bfloat162float(h1.y));
        *(__nv_bfloat162*)(yh + o1 + n8 * 8) = h0;
        *(__nv_bfloat162*)(yh + o2 + n8 * 8) = h1;
        *(__nv_bfloat162*)(yl + o1 + n8 * 8) = l0;
        *(__nv_bfloat162*)(yl + o2 + n8 * 8) = l1;
    }
}

// ---------------------------------------------------------------------------
// act = silu(gate)*up fused with bf16 hi/lo split output
// ---------------------------------------------------------------------------
__global__ void act_split_kernel(const float* __restrict__ gate,
                                 const float* __restrict__ up,
                                 __nv_bfloat16* __restrict__ oh,
                                 __nv_bfloat16* __restrict__ ol)
{
    const size_t i = (size_t)blockIdx.x * blockDim.x + threadIdx.x;
    float4 g = *(const float4*)(gate + i * 4);
    float4 u = *(const float4*)(up + i * 4);
    float o[4];
    o[0] = g.x / (1.f + __expf(-g.x)) * u.x;
    o[1] = g.y / (1.f + __expf(-g.y)) * u.y;
    o[2] = g.z / (1.f + __expf(-g.z)) * u.z;
    o[3] = g.w / (1.f + __expf(-g.w)) * u.w;
    __nv_bfloat16 hb[4], lb[4];
    #pragma unroll
    for (int j = 0; j < 4; j++) {
        hb[j] = __float2bfloat16(o[j]);
        lb[j] = __float2bfloat16(o[j] - __bfloat162float(hb[j]));
    }
    *(uint2*)(oh + i * 4) = *(uint2*)hb;
    *(uint2*)(ol + i * 4) = *(uint2*)lb;
}

// ---------------------------------------------------------------------------
// Launch
// ---------------------------------------------------------------------------
static inline int cdiv(long long a, long long b) { return (int)((a + b - 1) / b); }

extern "C" void kernel_launch(void* const* d_in, const int* in_sizes, int n_in,
                              void* d_out, int out_size)
{
    const float* x     = (const float*)d_in[0];
    const float* rc    = (const float*)d_in[1];
    const float* rs    = (const float*)d_in[2];
    const float* lerpw = (const float*)d_in[3];
    const float* lerpb = (const float*)d_in[4];
    const float* anw   = (const float*)d_in[5];
    const float* wqkv  = (const float*)d_in[6];
    const float* qnw   = (const float*)d_in[7];
    const float* knw   = (const float*)d_in[8];
    const float* qpb   = (const float*)d_in[9];
    const float* kpb   = (const float*)d_in[10];
    const float* ddw   = (const float*)d_in[11];
    const float* ddb   = (const float*)d_in[12];
    const float* wo    = (const float*)d_in[13];
    const float* mnw   = (const float*)d_in[14];
    const float* gw    = (const float*)d_in[15];
    const float* uw    = (const float*)d_in[16];
    const float* dw    = (const float*)d_in[17];
    float* out = (float*)d_out;

    float *glin, *xmix, *qkv, *dd, *cs, *qt, *kt, *vt, *x2, *gate, *up;
    __nv_bfloat16 *ah, *al, *wh, *wl;
    cudaGetSymbolAddress((void**)&glin, s_glin);
    cudaGetSymbolAddress((void**)&xmix, s_xmix);
    cudaGetSymbolAddress((void**)&qkv,  s_qkv);
    cudaGetSymbolAddress((void**)&dd,   s_dd);
    cudaGetSymbolAddress((void**)&cs,   s_csum);
    cudaGetSymbolAddress((void**)&qt,   s_qt);
    cudaGetSymbolAddress((void**)&kt,   s_kt);
    cudaGetSymbolAddress((void**)&vt,   s_vt);
    cudaGetSymbolAddress((void**)&x2,   s_x2);
    cudaGetSymbolAddress((void**)&gate, s_gate);
    cudaGetSymbolAddress((void**)&up,   s_up);
    cudaGetSymbolAddress((void**)&ah,   g_ah);
    cudaGetSymbolAddress((void**)&al,   g_al);
    cudaGetSymbolAddress((void**)&wh,   g_wh);
    cudaGetSymbolAddress((void**)&wl,   g_wl);

    cudaFuncSetAttribute(mma_gemm,
                         cudaFuncAttributeMaxDynamicSharedMemorySize, 2 * BUFB);
    cudaFuncSetAttribute(flash_tc,
                         cudaFuncAttributeMaxDynamicSharedMemorySize, FSMEM);

    const dim3 blk(256);
    const int GSM = 2 * BUFB;

    #define CONV(src, dh, dl, r, c, rp, cp) \
        convsplit<<<cdiv((long long)(rp) * (cp), 256), blk>>>(src, dh, dl, r, c, rp, cp)

    // 1. glin = x @ lerp_w^T + lerp_b
    CONV(x, ah, al, M_, D_, M_, D_);
    CONV(lerpw, wh, wl, D_, D_, D_, D_);
    mma_gemm<<<dim3(8, 32), blk, GSM>>>(ah, al, wh, wl, lerpb, nullptr, glin, D_, 32, D_, 1);
    // 2. xmix (fp32 + bf16 split)
    mix_split_kernel<<<(M_ * D_ / 4) / 256, blk>>>(x, glin, xmix, ah, al);
    // 3. dd = xmix @ dd_w^T + dd_b
    CONV(ddw, wh, wl, 256, D_, 256, D_);
    mma_gemm<<<dim3(2, 32), blk, GSM>>>(ah, al, wh, wl, ddb, nullptr, dd, D_, 32, 256, 1);
    // 4. cumsum along T
    cumsumA<<<B_ * 16, blk>>>(dd, cs);
    cumsumB<<<B_, blk>>>(cs);
    cumsumC<<<B_ * 16, blk>>>(dd, cs);
    // 5. h = rmsnorm(xmix) -> bf16 split
    rmsnorm_split_kernel<<<M_, blk>>>(xmix, anw, ah, al);
    // 6. qkv = h @ w_qkv^T
    CONV(wqkv, wh, wl, 3 * D_, D_, 3 * D_, D_);
    mma_gemm<<<dim3(24, 32), blk, GSM>>>(ah, al, wh, wl, nullptr, nullptr, qkv, D_, 32, 3 * D_, 0);
    // 7. q/k transform
    qkv_transform_kernel<<<(B_ * T_ * NH_) / 8, blk>>>(qkv, dd, rc, rs, qnw, knw,
                                                       qpb, kpb, qt, kt, vt);
    // 8. flash attention (tf32 mma) -> y bf16 split
    flash_tc<<<dim3(T_ / 128, B_ * NH_), blk, FSMEM>>>(qt, kt, vt, ah, al);
    // 9. x2 = xmix + y @ w_o^T
    CONV(wo, wh, wl, D_, D_, D_, D_);
    mma_gemm<<<dim3(8, 32), blk, GSM>>>(ah, al, wh, wl, nullptr, xmix, x2, D_, 32, D_, 2);
    // 10. h = rmsnorm(x2) -> bf16 split
    rmsnorm_split_kernel<<<M_, blk>>>(x2, mnw, ah, al);
    // 11/12. gate, up
    CONV(gw, wh, wl, FFN_, D_, FFNP, D_);
    mma_gemm<<<dim3(22, 32), blk, GSM>>>(ah, al, wh, wl, nullptr, nullptr, gate, D_, 32, FFNP, 0);
    CONV(uw, wh, wl, FFN_, D_, FFNP, D_);
    mma_gemm<<<dim3(22, 32), blk, GSM>>>(ah, al, wh, wl, nullptr, nullptr, up, D_, 32, FFNP, 0);
    // 13. act = silu(gate)*up -> bf16 split
    act_split_kernel<<<(M_ * FFNP / 4) / 256, blk>>>(gate, up, ah, al);
    // 14. out = x2 + act @ down_w^T
    CONV(dw, wh, wl, D_, FFN_, D_, FFNP);
    mma_gemm<<<dim3(8, 32), blk, GSM>>>(ah, al, wh, wl, nullptr, x2, out, FFNP, 88, D_, 2);
}